// round 7
// baseline (speedup 1.0000x reference)
#include <cuda_runtime.h>
#include <cuda_bf16.h>
#include <math.h>
#include <cstdint>

#define N_TOK_MAX 11136
#define IN_DIM    256
#define E_DIM     256
#define NHEAD     8
#define HDIM      32
#define NB        16
#define QKV_DIM   768

typedef unsigned int u32;

// Scratch (device globals: allocation-free rule)
__device__ float g_qkv[(size_t)N_TOK_MAX * QKV_DIM];   // [N, 768]
__device__ float g_att[(size_t)N_TOK_MAX * E_DIM];     // [N, 256]
__device__ int   g_start[NB + 1];

// ---- tf32 helpers -----------------------------------------------------------
__device__ __forceinline__ void split_tf32(float v, u32& hi, u32& lo) {
    asm("cvt.rna.tf32.f32 %0, %1;" : "=r"(hi) : "f"(v));
    float r = v - __uint_as_float(hi);
    asm("cvt.rna.tf32.f32 %0, %1;" : "=r"(lo) : "f"(r));
}

// D += A(m16k8,row) * B(k8n8,col)  tf32->f32
__device__ __forceinline__ void mma8(float* c, const u32* a, u32 b0, u32 b1) {
    asm volatile(
        "mma.sync.aligned.m16n8k8.row.col.f32.tf32.tf32.f32 "
        "{%0,%1,%2,%3}, {%4,%5,%6,%7}, {%8,%9}, {%0,%1,%2,%3};"
        : "+f"(c[0]), "+f"(c[1]), "+f"(c[2]), "+f"(c[3])
        : "r"(a[0]), "r"(a[1]), "r"(a[2]), "r"(a[3]), "r"(b0), "r"(b1));
}

// 3xTF32: C += Ahi*Bhi + Ahi*Blo + Alo*Bhi
__device__ __forceinline__ void mma3(float* c, const u32* ah, const u32* al,
                                     u32 bh0, u32 bh1, u32 bl0, u32 bl1) {
    mma8(c, ah, bh0, bh1);
    mma8(c, ah, bl0, bl1);
    mma8(c, al, bh0, bh1);
}

// ---------------------------------------------------------------------------
// Kernel 1: histogram of sorted batch ids -> segment start offsets
// ---------------------------------------------------------------------------
__global__ void hist_kernel(const int* __restrict__ ids, int n) {
    __shared__ int cnt[NB];
    int t = threadIdx.x;
    if (t < NB) cnt[t] = 0;
    __syncthreads();
    for (int i = t; i < n; i += blockDim.x)
        atomicAdd(&cnt[ids[i]], 1);
    __syncthreads();
    if (t == 0) {
        int acc = 0;
        for (int v = 0; v < NB; v++) { g_start[v] = acc; acc += cnt[v]; }
        g_start[NB] = acc;
    }
}

// ---------------------------------------------------------------------------
// 3xTF32 MMA GEMM: C[M,N] = A[M,K] @ B[N,K]^T + bias[N]
// Block tile 64x64, 128 threads (4 warps; warp w -> rows 16w..16w+15).
// B pre-split into hi/lo tf32 smem tiles at load (removes x4-duplicated
// in-loop splits). Register-staged pipeline overlaps global loads w/ mma.
// ---------------------------------------------------------------------------
__global__ __launch_bounds__(128) void mma_gemm_kernel(
    const float* __restrict__ A, const float* __restrict__ Bw,
    const float* __restrict__ bias, float* __restrict__ C,
    int M, int N, int K)
{
    __shared__ float As[64][36];
    __shared__ u32   Bh[64][36];
    __shared__ u32   Bl[64][36];

    const int t    = threadIdx.x;
    const int lane = t & 31, w = t >> 5;
    const int g    = lane >> 2, tig = lane & 3;
    const int m0   = blockIdx.y * 64;
    const int n0   = blockIdx.x * 64;

    float acc[8][4];
#pragma unroll
    for (int i = 0; i < 8; i++)
#pragma unroll
        for (int j = 0; j < 4; j++) acc[i][j] = 0.f;

    const int lr = t >> 1, lc = (t & 1) * 16;   // loader: row, 16-col slab
    const float* aPtr = A  + (size_t)min(m0 + lr, M - 1) * K + lc;
    const float* bPtr = Bw + (size_t)(n0 + lr) * K + lc;

    float4 aReg[4], bReg[4];
#pragma unroll
    for (int q = 0; q < 4; q++) {
        aReg[q] = *(const float4*)(aPtr + q * 4);
        bReg[q] = *(const float4*)(bPtr + q * 4);
    }

    for (int kc = 0; kc < K; kc += 32) {
        // store staged regs to smem; split B on the way
#pragma unroll
        for (int q = 0; q < 4; q++) {
            *(float4*)&As[lr][lc + q * 4] = aReg[q];
            const float bv[4] = {bReg[q].x, bReg[q].y, bReg[q].z, bReg[q].w};
#pragma unroll
            for (int e = 0; e < 4; e++) {
                u32 hi, lo;
                split_tf32(bv[e], hi, lo);
                Bh[lr][lc + q * 4 + e] = hi;
                Bl[lr][lc + q * 4 + e] = lo;
            }
        }
        __syncthreads();

        // prefetch next chunk while mma runs
        if (kc + 32 < K) {
#pragma unroll
            for (int q = 0; q < 4; q++) {
                aReg[q] = *(const float4*)(aPtr + kc + 32 + q * 4);
                bReg[q] = *(const float4*)(bPtr + kc + 32 + q * 4);
            }
        }

#pragma unroll
        for (int ks = 0; ks < 4; ks++) {
            const int k0 = ks * 8;
            u32 ah[4], al[4];
            split_tf32(As[16 * w + g][k0 + tig],         ah[0], al[0]);
            split_tf32(As[16 * w + g + 8][k0 + tig],     ah[1], al[1]);
            split_tf32(As[16 * w + g][k0 + tig + 4],     ah[2], al[2]);
            split_tf32(As[16 * w + g + 8][k0 + tig + 4], ah[3], al[3]);
#pragma unroll
            for (int nt = 0; nt < 8; nt++) {
                u32 bh0 = Bh[nt * 8 + g][k0 + tig];
                u32 bh1 = Bh[nt * 8 + g][k0 + tig + 4];
                u32 bl0 = Bl[nt * 8 + g][k0 + tig];
                u32 bl1 = Bl[nt * 8 + g][k0 + tig + 4];
                mma3(acc[nt], ah, al, bh0, bh1, bl0, bl1);
            }
        }
        __syncthreads();
    }

    const int ra = m0 + 16 * w + g;
    const int rb = ra + 8;
#pragma unroll
    for (int nt = 0; nt < 8; nt++) {
        int col = n0 + nt * 8 + 2 * tig;
        float b0 = bias[col], b1 = bias[col + 1];
        if (ra < M) {
            C[(size_t)ra * N + col]     = acc[nt][0] + b0;
            C[(size_t)ra * N + col + 1] = acc[nt][1] + b1;
        }
        if (rb < M) {
            C[(size_t)rb * N + col]     = acc[nt][2] + b0;
            C[(size_t)rb * N + col + 1] = acc[nt][3] + b1;
        }
    }
}

// ---------------------------------------------------------------------------
// Kernel 3: varlen flash attention with 3xTF32 mma.
// Block = (64-query tile, segment, head). 128 threads, 4 warps.
// Q fragments pre-split into registers (loop-invariant); K/V pre-split into
// hi/lo smem tiles at load. PV reuses S fragments via even/odd V-row permute.
// ---------------------------------------------------------------------------
__global__ __launch_bounds__(128) void attn_mma_kernel(int n) {
    const int seg = blockIdx.y;
    const int h   = blockIdx.z;
    const int qs  = g_start[seg];
    const int qe  = g_start[seg + 1];
    const int q0  = qs + blockIdx.x * 64;
    if (q0 >= qe) return;

    __shared__ float Qs[64][36];
    __shared__ u32   Kh[64][36];
    __shared__ u32   Kl[64][36];
    __shared__ u32   Vh[64][36];   // V rows permuted even-then-odd per 8-group
    __shared__ u32   Vl[64][36];

    const int t    = threadIdx.x;
    const int lane = t & 31, w = t >> 5;
    const int g    = lane >> 2, tig = lane & 3;

    const float* __restrict__ qkv = g_qkv;
    const int qoff = h * 96;
    const int koff = h * 96 + 32;
    const int voff = h * 96 + 64;

    const int lr = t >> 1, lc = (t & 1) * 16;

    // Q tile load (once)
    {
        int row = min(q0 + lr, qe - 1);
        const float* p = qkv + (size_t)row * QKV_DIM + qoff + lc;
        *(float4*)&Qs[lr][lc]      = *(const float4*)p;
        *(float4*)&Qs[lr][lc + 4]  = *(const float4*)(p + 4);
        *(float4*)&Qs[lr][lc + 8]  = *(const float4*)(p + 8);
        *(float4*)&Qs[lr][lc + 12] = *(const float4*)(p + 12);
    }
    __syncthreads();

    // loop-invariant Q fragments, split once into registers
    u32 qh[4][4], ql[4][4];
#pragma unroll
    for (int ks = 0; ks < 4; ks++) {
        const int k0 = ks * 8;
        split_tf32(Qs[16 * w + g][k0 + tig],         qh[ks][0], ql[ks][0]);
        split_tf32(Qs[16 * w + g + 8][k0 + tig],     qh[ks][1], ql[ks][1]);
        split_tf32(Qs[16 * w + g][k0 + tig + 4],     qh[ks][2], ql[ks][2]);
        split_tf32(Qs[16 * w + g + 8][k0 + tig + 4], qh[ks][3], ql[ks][3]);
    }

    // V row permutation within 8-group: key i -> row (i even ? i/2 : 4 + i/2)
    const int i8 = lr & 7;
    const int pr = (lr & ~7) | ((i8 & 1) ? 4 + (i8 >> 1) : (i8 >> 1));

    float m_a = -1e30f, m_b = -1e30f;
    float l_a = 0.f, l_b = 0.f;
    float out[4][4];
#pragma unroll
    for (int i = 0; i < 4; i++)
#pragma unroll
        for (int j = 0; j < 4; j++) out[i][j] = 0.f;

    const float scale = 0.17677669529663687f;   // 1/sqrt(32)

    for (int j0 = qs; j0 < qe; j0 += 64) {
        const int nk = min(64, qe - j0);
        // K + permuted-V chunk load with hi/lo split at load time
        {
            int row = min(j0 + lr, qe - 1);
            const float* kp = qkv + (size_t)row * QKV_DIM + koff + lc;
            const float* vp = qkv + (size_t)row * QKV_DIM + voff + lc;
#pragma unroll
            for (int q = 0; q < 4; q++) {
                float4 kv = *(const float4*)(kp + q * 4);
                float4 vv = *(const float4*)(vp + q * 4);
                const float ka[4] = {kv.x, kv.y, kv.z, kv.w};
                const float va[4] = {vv.x, vv.y, vv.z, vv.w};
#pragma unroll
                for (int e = 0; e < 4; e++) {
                    u32 hi, lo;
                    split_tf32(ka[e], hi, lo);
                    Kh[lr][lc + q * 4 + e] = hi;
                    Kl[lr][lc + q * 4 + e] = lo;
                    split_tf32(va[e], hi, lo);
                    Vh[pr][lc + q * 4 + e] = hi;
                    Vl[pr][lc + q * 4 + e] = lo;
                }
            }
        }
        __syncthreads();

        // ---- S = Q @ K^T (3xTF32), 8 key-tiles ----
        float S[8][4];
#pragma unroll
        for (int i = 0; i < 8; i++)
#pragma unroll
            for (int j = 0; j < 4; j++) S[i][j] = 0.f;

#pragma unroll
        for (int ks = 0; ks < 4; ks++) {
            const int k0 = ks * 8;
#pragma unroll
            for (int nt = 0; nt < 8; nt++) {
                u32 bh0 = Kh[nt * 8 + g][k0 + tig];
                u32 bh1 = Kh[nt * 8 + g][k0 + tig + 4];
                u32 bl0 = Kl[nt * 8 + g][k0 + tig];
                u32 bl1 = Kl[nt * 8 + g][k0 + tig + 4];
                mma3(S[nt], qh[ks], ql[ks], bh0, bh1, bl0, bl1);
            }
        }

        // scale + key mask
#pragma unroll
        for (int nt = 0; nt < 8; nt++) {
            int c0 = nt * 8 + 2 * tig;
            bool ok0 = c0 < nk, ok1 = (c0 + 1) < nk;
            S[nt][0] = ok0 ? S[nt][0] * scale : -1e30f;
            S[nt][1] = ok1 ? S[nt][1] * scale : -1e30f;
            S[nt][2] = ok0 ? S[nt][2] * scale : -1e30f;
            S[nt][3] = ok1 ? S[nt][3] * scale : -1e30f;
        }

        // row max: row g uses S[.][0..1], row g+8 uses S[.][2..3]
        float ca = -1e30f, cb = -1e30f;
#pragma unroll
        for (int nt = 0; nt < 8; nt++) {
            ca = fmaxf(ca, fmaxf(S[nt][0], S[nt][1]));
            cb = fmaxf(cb, fmaxf(S[nt][2], S[nt][3]));
        }
#pragma unroll
        for (int d = 1; d <= 2; d <<= 1) {
            ca = fmaxf(ca, __shfl_xor_sync(0xffffffffu, ca, d));
            cb = fmaxf(cb, __shfl_xor_sync(0xffffffffu, cb, d));
        }
        float mn_a = fmaxf(m_a, ca);
        float mn_b = fmaxf(m_b, cb);
        float sf_a = __expf(m_a - mn_a);
        float sf_b = __expf(m_b - mn_b);
        m_a = mn_a; m_b = mn_b;

        // P = exp(S - m), partial row sums
        float sa = 0.f, sb = 0.f;
#pragma unroll
        for (int nt = 0; nt < 8; nt++) {
            S[nt][0] = __expf(S[nt][0] - mn_a);
            S[nt][1] = __expf(S[nt][1] - mn_a);
            S[nt][2] = __expf(S[nt][2] - mn_b);
            S[nt][3] = __expf(S[nt][3] - mn_b);
            sa += S[nt][0] + S[nt][1];
            sb += S[nt][2] + S[nt][3];
        }
#pragma unroll
        for (int d = 1; d <= 2; d <<= 1) {
            sa += __shfl_xor_sync(0xffffffffu, sa, d);
            sb += __shfl_xor_sync(0xffffffffu, sb, d);
        }
        l_a = l_a * sf_a + sa;
        l_b = l_b * sf_b + sb;
#pragma unroll
        for (int nt = 0; nt < 4; nt++) {
            out[nt][0] *= sf_a; out[nt][1] *= sf_a;
            out[nt][2] *= sf_b; out[nt][3] *= sf_b;
        }

        // ---- out += P @ V (3xTF32). A-frags = S-frags directly
        //   (valid because Vh/Vl rows are even/odd-permuted per 8-group).
#pragma unroll
        for (int kt = 0; kt < 8; kt++) {
            u32 ah[4], al[4];
            split_tf32(S[kt][0], ah[0], al[0]);
            split_tf32(S[kt][2], ah[1], al[1]);
            split_tf32(S[kt][1], ah[2], al[2]);
            split_tf32(S[kt][3], ah[3], al[3]);
#pragma unroll
            for (int nt = 0; nt < 4; nt++) {
                u32 bh0 = Vh[kt * 8 + tig][nt * 8 + g];
                u32 bh1 = Vh[kt * 8 + tig + 4][nt * 8 + g];
                u32 bl0 = Vl[kt * 8 + tig][nt * 8 + g];
                u32 bl1 = Vl[kt * 8 + tig + 4][nt * 8 + g];
                mma3(out[nt], ah, al, bh0, bh1, bl0, bl1);
            }
        }
        __syncthreads();   // before next chunk overwrites K/V tiles
    }

    const float inv_a = 1.0f / l_a;
    const float inv_b = 1.0f / l_b;
    const int ra = q0 + 16 * w + g;
    const int rb = ra + 8;
#pragma unroll
    for (int nt = 0; nt < 4; nt++) {
        int d = nt * 8 + 2 * tig;
        if (ra < qe) {
            float* p = g_att + (size_t)ra * E_DIM + h * HDIM + d;
            p[0] = out[nt][0] * inv_a;
            p[1] = out[nt][1] * inv_a;
        }
        if (rb < qe) {
            float* p = g_att + (size_t)rb * E_DIM + h * HDIM + d;
            p[0] = out[nt][2] * inv_b;
            p[1] = out[nt][3] * inv_b;
        }
    }
}

// ---------------------------------------------------------------------------
extern "C" void kernel_launch(void* const* d_in, const int* in_sizes, int n_in,
                              void* d_out, int out_size) {
    const float* x      = (const float*)d_in[0];
    const int*   ids    = (const int*)  d_in[1];
    const float* qkv_w  = (const float*)d_in[2];
    const float* qkv_b  = (const float*)d_in[3];
    const float* o_w    = (const float*)d_in[4];
    const float* o_b    = (const float*)d_in[5];
    float*       out    = (float*)d_out;
    const int n = in_sizes[1];   // token count

    hist_kernel<<<1, 256>>>(ids, n);

    float* qkv_out = nullptr;
    cudaGetSymbolAddress((void**)&qkv_out, g_qkv);
    float* att_out = nullptr;
    cudaGetSymbolAddress((void**)&att_out, g_att);

    dim3 g_qkv_grid(QKV_DIM / 64, (n + 63) / 64);
    mma_gemm_kernel<<<g_qkv_grid, 128>>>(x, qkv_w, qkv_b, qkv_out, n, QKV_DIM, IN_DIM);

    dim3 g_attn((n + 63) / 64, NB, NHEAD);
    attn_mma_kernel<<<g_attn, 128>>>(n);

    dim3 g_proj(E_DIM / 64, (n + 63) / 64);
    mma_gemm_kernel<<<g_proj, 128>>>(att_out, o_w, o_b, out, n, E_DIM, E_DIM);
}

// round 9
// speedup vs baseline: 1.0608x; 1.0608x over previous
#include <cuda_runtime.h>
#include <cuda_bf16.h>
#include <math.h>
#include <cstdint>

#define N_TOK_MAX 11136
#define IN_DIM    256
#define E_DIM     256
#define NHEAD     8
#define HDIM      32
#define NB        16
#define QKV_DIM   768

typedef unsigned int u32;

// Scratch (device globals: allocation-free rule)
__device__ float g_qkv[(size_t)N_TOK_MAX * QKV_DIM];   // [N, 768]
__device__ float g_att[(size_t)N_TOK_MAX * E_DIM];     // [N, 256]
__device__ int   g_start[NB + 1];

// ---- tf32 helpers -----------------------------------------------------------
__device__ __forceinline__ void split_tf32(float v, u32& hi, u32& lo) {
    asm("cvt.rna.tf32.f32 %0, %1;" : "=r"(hi) : "f"(v));
    float r = v - __uint_as_float(hi);
    asm("cvt.rna.tf32.f32 %0, %1;" : "=r"(lo) : "f"(r));
}

// D += A(m16k8,row) * B(k8n8,col)  tf32->f32
__device__ __forceinline__ void mma8(float* c, const u32* a, u32 b0, u32 b1) {
    asm volatile(
        "mma.sync.aligned.m16n8k8.row.col.f32.tf32.tf32.f32 "
        "{%0,%1,%2,%3}, {%4,%5,%6,%7}, {%8,%9}, {%0,%1,%2,%3};"
        : "+f"(c[0]), "+f"(c[1]), "+f"(c[2]), "+f"(c[3])
        : "r"(a[0]), "r"(a[1]), "r"(a[2]), "r"(a[3]), "r"(b0), "r"(b1));
}

// 3xTF32: C += Ahi*Bhi + Ahi*Blo + Alo*Bhi
__device__ __forceinline__ void mma3(float* c, const u32* ah, const u32* al,
                                     u32 bh0, u32 bh1, u32 bl0, u32 bl1) {
    mma8(c, ah, bh0, bh1);
    mma8(c, ah, bl0, bl1);
    mma8(c, al, bh0, bh1);
}

// ---------------------------------------------------------------------------
// Kernel 1: histogram of sorted batch ids -> segment start offsets
// ---------------------------------------------------------------------------
__global__ void hist_kernel(const int* __restrict__ ids, int n) {
    __shared__ int cnt[NB];
    int t = threadIdx.x;
    if (t < NB) cnt[t] = 0;
    __syncthreads();
    for (int i = t; i < n; i += blockDim.x)
        atomicAdd(&cnt[ids[i]], 1);
    __syncthreads();
    if (t == 0) {
        int acc = 0;
        for (int v = 0; v < NB; v++) { g_start[v] = acc; acc += cnt[v]; }
        g_start[NB] = acc;
    }
}

// ---------------------------------------------------------------------------
// 3xTF32 MMA GEMM: C[M,N] = A[M,K] @ B[N,K]^T + bias[N]
// Block tile (NW*16) x 64, NW warps; warp w -> rows 16w..16w+15.
// K consumed in chunks of 32 (4 k8-steps). In-loop tf32 splits (R6 style:
// measured better than pre-split smem tiles due to occupancy).
// ---------------------------------------------------------------------------
template<int NW>
__global__ __launch_bounds__(NW * 32) void mma_gemm_kernel(
    const float* __restrict__ A, const float* __restrict__ Bw,
    const float* __restrict__ bias, float* __restrict__ C,
    int M, int N, int K)
{
    __shared__ float As[NW * 16][36];
    __shared__ float Bs[64][36];

    const int t    = threadIdx.x;
    const int lane = t & 31, w = t >> 5;
    const int g    = lane >> 2, tig = lane & 3;
    const int m0   = blockIdx.y * (NW * 16);
    const int n0   = blockIdx.x * 64;

    float acc[8][4];
#pragma unroll
    for (int i = 0; i < 8; i++)
#pragma unroll
        for (int j = 0; j < 4; j++) acc[i][j] = 0.f;

    // A loader: rows t>>1 (covers NW*16), 16-col slab
    const int lrA = t >> 1, lcA = (t & 1) * 16;

    for (int kc = 0; kc < K; kc += 32) {
        {
            int ga = min(m0 + lrA, M - 1);
            const float* ap = A + (size_t)ga * K + kc + lcA;
#pragma unroll
            for (int q = 0; q < 4; q++)
                *(float4*)&As[lrA][lcA + q * 4] = *(const float4*)(ap + q * 4);
        }
        if (NW == 4) {
            const int lrB = t >> 1, lcB = (t & 1) * 16;
            const float* bp = Bw + (size_t)(n0 + lrB) * K + kc + lcB;
#pragma unroll
            for (int q = 0; q < 4; q++)
                *(float4*)&Bs[lrB][lcB + q * 4] = *(const float4*)(bp + q * 4);
        } else {
            const int lrB = t >> 2, lcB = (t & 3) * 8;
            const float* bp = Bw + (size_t)(n0 + lrB) * K + kc + lcB;
#pragma unroll
            for (int q = 0; q < 2; q++)
                *(float4*)&Bs[lrB][lcB + q * 4] = *(const float4*)(bp + q * 4);
        }
        __syncthreads();

#pragma unroll
        for (int ks = 0; ks < 4; ks++) {
            const int k0 = ks * 8;
            u32 ah[4], al[4];
            split_tf32(As[16 * w + g][k0 + tig],         ah[0], al[0]);
            split_tf32(As[16 * w + g + 8][k0 + tig],     ah[1], al[1]);
            split_tf32(As[16 * w + g][k0 + tig + 4],     ah[2], al[2]);
            split_tf32(As[16 * w + g + 8][k0 + tig + 4], ah[3], al[3]);
#pragma unroll
            for (int nt = 0; nt < 8; nt++) {
                u32 bh0, bl0, bh1, bl1;
                split_tf32(Bs[nt * 8 + g][k0 + tig],     bh0, bl0);
                split_tf32(Bs[nt * 8 + g][k0 + tig + 4], bh1, bl1);
                mma3(acc[nt], ah, al, bh0, bh1, bl0, bl1);
            }
        }
        __syncthreads();
    }

    const int ra = m0 + 16 * w + g;
    const int rb = ra + 8;
#pragma unroll
    for (int nt = 0; nt < 8; nt++) {
        int col = n0 + nt * 8 + 2 * tig;
        float b0 = bias[col], b1 = bias[col + 1];
        if (ra < M) {
            C[(size_t)ra * N + col]     = acc[nt][0] + b0;
            C[(size_t)ra * N + col + 1] = acc[nt][1] + b1;
        }
        if (rb < M) {
            C[(size_t)rb * N + col]     = acc[nt][2] + b0;
            C[(size_t)rb * N + col + 1] = acc[nt][3] + b1;
        }
    }
}

// ---------------------------------------------------------------------------
// Kernel 3: varlen flash attention with 3xTF32 mma.
// Block = (128-query tile, segment, head). 256 threads, 8 warps.
// Warp w: query rows 16w..16w+15. K/V smem tiles (64 keys) amortized over
// 2x the queries of R6. PV reuses S fragments via even/odd V-row permute.
// ---------------------------------------------------------------------------
__global__ __launch_bounds__(256) void attn_mma_kernel(int n) {
    const int seg = blockIdx.y;
    const int h   = blockIdx.z;
    const int qs  = g_start[seg];
    const int qe  = g_start[seg + 1];
    const int q0  = qs + blockIdx.x * 128;
    if (q0 >= qe) return;

    __shared__ float Qs[128][36];
    __shared__ float Ks[64][36];
    __shared__ float Vp[64][36];   // V rows permuted even-then-odd per 8-group

    const int t    = threadIdx.x;
    const int lane = t & 31, w = t >> 5;
    const int g    = lane >> 2, tig = lane & 3;

    const float* __restrict__ qkv = g_qkv;
    const int qoff = h * 96;
    const int koff = h * 96 + 32;
    const int voff = h * 96 + 64;

    // Q tile load (once): row = t>>1 (0..127), 16-col slab
    {
        int lr = t >> 1, lc = (t & 1) * 16;
        int row = min(q0 + lr, qe - 1);
        const float* p = qkv + (size_t)row * QKV_DIM + qoff + lc;
#pragma unroll
        for (int q = 0; q < 4; q++)
            *(float4*)&Qs[lr][lc + q * 4] = *(const float4*)(p + q * 4);
    }

    // K/V loader: row = t>>2 (0..63), 8-col slab
    const int lrk = t >> 2, lck = (t & 3) * 8;
    // V row permutation within 8-group: key i -> row (i even ? i/2 : 4 + i/2)
    const int i8 = lrk & 7;
    const int pr = (lrk & ~7) | ((i8 & 1) ? 4 + (i8 >> 1) : (i8 >> 1));

    float m_a = -1e30f, m_b = -1e30f;
    float l_a = 0.f, l_b = 0.f;
    float out[4][4];
#pragma unroll
    for (int i = 0; i < 4; i++)
#pragma unroll
        for (int j = 0; j < 4; j++) out[i][j] = 0.f;

    const float scale = 0.17677669529663687f;   // 1/sqrt(32)

    for (int j0 = qs; j0 < qe; j0 += 64) {
        const int nk = min(64, qe - j0);
        // K + permuted-V chunk load
        {
            int row = min(j0 + lrk, qe - 1);
            const float* kp = qkv + (size_t)row * QKV_DIM + koff + lck;
            const float* vp = qkv + (size_t)row * QKV_DIM + voff + lck;
            *(float4*)&Ks[lrk][lck]     = *(const float4*)kp;
            *(float4*)&Ks[lrk][lck + 4] = *(const float4*)(kp + 4);
            *(float4*)&Vp[pr][lck]      = *(const float4*)vp;
            *(float4*)&Vp[pr][lck + 4]  = *(const float4*)(vp + 4);
        }
        __syncthreads();

        // ---- S = Q @ K^T (3xTF32), 8 key-tiles ----
        float S[8][4];
#pragma unroll
        for (int i = 0; i < 8; i++)
#pragma unroll
            for (int j = 0; j < 4; j++) S[i][j] = 0.f;

#pragma unroll
        for (int ks = 0; ks < 4; ks++) {
            const int k0 = ks * 8;
            u32 ah[4], al[4];
            split_tf32(Qs[16 * w + g][k0 + tig],         ah[0], al[0]);
            split_tf32(Qs[16 * w + g + 8][k0 + tig],     ah[1], al[1]);
            split_tf32(Qs[16 * w + g][k0 + tig + 4],     ah[2], al[2]);
            split_tf32(Qs[16 * w + g + 8][k0 + tig + 4], ah[3], al[3]);
#pragma unroll
            for (int nt = 0; nt < 8; nt++) {
                u32 bh0, bl0, bh1, bl1;
                split_tf32(Ks[nt * 8 + g][k0 + tig],     bh0, bl0);
                split_tf32(Ks[nt * 8 + g][k0 + tig + 4], bh1, bl1);
                mma3(S[nt], ah, al, bh0, bh1, bl0, bl1);
            }
        }

        // scale + key mask
#pragma unroll
        for (int nt = 0; nt < 8; nt++) {
            int c0 = nt * 8 + 2 * tig;
            bool ok0 = c0 < nk, ok1 = (c0 + 1) < nk;
            S[nt][0] = ok0 ? S[nt][0] * scale : -1e30f;
            S[nt][1] = ok1 ? S[nt][1] * scale : -1e30f;
            S[nt][2] = ok0 ? S[nt][2] * scale : -1e30f;
            S[nt][3] = ok1 ? S[nt][3] * scale : -1e30f;
        }

        // row max: row g uses S[.][0..1], row g+8 uses S[.][2..3]
        float ca = -1e30f, cb = -1e30f;
#pragma unroll
        for (int nt = 0; nt < 8; nt++) {
            ca = fmaxf(ca, fmaxf(S[nt][0], S[nt][1]));
            cb = fmaxf(cb, fmaxf(S[nt][2], S[nt][3]));
        }
#pragma unroll
        for (int d = 1; d <= 2; d <<= 1) {
            ca = fmaxf(ca, __shfl_xor_sync(0xffffffffu, ca, d));
            cb = fmaxf(cb, __shfl_xor_sync(0xffffffffu, cb, d));
        }
        float mn_a = fmaxf(m_a, ca);
        float mn_b = fmaxf(m_b, cb);
        float sf_a = __expf(m_a - mn_a);
        float sf_b = __expf(m_b - mn_b);
        m_a = mn_a; m_b = mn_b;

        // P = exp(S - m), partial row sums
        float sa = 0.f, sb = 0.f;
#pragma unroll
        for (int nt = 0; nt < 8; nt++) {
            S[nt][0] = __expf(S[nt][0] - mn_a);
            S[nt][1] = __expf(S[nt][1] - mn_a);
            S[nt][2] = __expf(S[nt][2] - mn_b);
            S[nt][3] = __expf(S[nt][3] - mn_b);
            sa += S[nt][0] + S[nt][1];
            sb += S[nt][2] + S[nt][3];
        }
#pragma unroll
        for (int d = 1; d <= 2; d <<= 1) {
            sa += __shfl_xor_sync(0xffffffffu, sa, d);
            sb += __shfl_xor_sync(0xffffffffu, sb, d);
        }
        l_a = l_a * sf_a + sa;
        l_b = l_b * sf_b + sb;
#pragma unroll
        for (int nt = 0; nt < 4; nt++) {
            out[nt][0] *= sf_a; out[nt][1] *= sf_a;
            out[nt][2] *= sf_b; out[nt][3] *= sf_b;
        }

        // ---- out += P @ V (3xTF32). A-frags = S-frags directly
        //   (valid because Vp rows are even/odd-permuted per 8-group).
#pragma unroll
        for (int kt = 0; kt < 8; kt++) {
            u32 ah[4], al[4];
            split_tf32(S[kt][0], ah[0], al[0]);
            split_tf32(S[kt][2], ah[1], al[1]);
            split_tf32(S[kt][1], ah[2], al[2]);
            split_tf32(S[kt][3], ah[3], al[3]);
#pragma unroll
            for (int nt = 0; nt < 4; nt++) {
                u32 bh0, bl0, bh1, bl1;
                split_tf32(Vp[kt * 8 + tig][nt * 8 + g],     bh0, bl0);
                split_tf32(Vp[kt * 8 + tig + 4][nt * 8 + g], bh1, bl1);
                mma3(out[nt], ah, al, bh0, bh1, bl0, bl1);
            }
        }
        __syncthreads();   // before next chunk overwrites Ks/Vp
    }

    const float inv_a = 1.0f / l_a;
    const float inv_b = 1.0f / l_b;
    const int ra = q0 + 16 * w + g;
    const int rb = ra + 8;
#pragma unroll
    for (int nt = 0; nt < 4; nt++) {
        int d = nt * 8 + 2 * tig;
        if (ra < qe) {
            float* p = g_att + (size_t)ra * E_DIM + h * HDIM + d;
            p[0] = out[nt][0] * inv_a;
            p[1] = out[nt][1] * inv_a;
        }
        if (rb < qe) {
            float* p = g_att + (size_t)rb * E_DIM + h * HDIM + d;
            p[0] = out[nt][2] * inv_b;
            p[1] = out[nt][3] * inv_b;
        }
    }
}

// ---------------------------------------------------------------------------
extern "C" void kernel_launch(void* const* d_in, const int* in_sizes, int n_in,
                              void* d_out, int out_size) {
    const float* x      = (const float*)d_in[0];
    const int*   ids    = (const int*)  d_in[1];
    const float* qkv_w  = (const float*)d_in[2];
    const float* qkv_b  = (const float*)d_in[3];
    const float* o_w    = (const float*)d_in[4];
    const float* o_b    = (const float*)d_in[5];
    float*       out    = (float*)d_out;
    const int n = in_sizes[1];   // token count

    hist_kernel<<<1, 256>>>(ids, n);

    float* qkv_out = nullptr;
    cudaGetSymbolAddress((void**)&qkv_out, g_qkv);
    float* att_out = nullptr;
    cudaGetSymbolAddress((void**)&att_out, g_att);

    // QKV: 128-row tiles, 8 warps (B-tile work amortized over 2x rows)
    dim3 g_qkv_grid(QKV_DIM / 64, (n + 127) / 128);
    mma_gemm_kernel<8><<<g_qkv_grid, 256>>>(x, qkv_w, qkv_b, qkv_out, n, QKV_DIM, IN_DIM);

    // Attention: 128-query tiles, 8 warps
    dim3 g_attn((n + 127) / 128, NB, NHEAD);
    attn_mma_kernel<<<g_attn, 256>>>(n);

    // Proj: R6 shape (64x64, 4 warps) — better grid quantization at N=256
    dim3 g_proj(E_DIM / 64, (n + 63) / 64);
    mma_gemm_kernel<4><<<g_proj, 128>>>(att_out, o_w, o_b, out, n, E_DIM, E_DIM);
}